// round 11
// baseline (speedup 1.0000x reference)
#include <cuda_runtime.h>
#include <cuda_fp16.h>
#include <math.h>

#define D 32
#define HP 16            // half-plane width (dims per edge pass)
#define F 64
#define MAXB 262144
#define MAXNE 500000

// Scratch (device globals — no allocation allowed)
// h and proj stored PLANE-MAJOR: [plane][row][16] so each edge pass gathers
// a 32B-aligned half-row and the per-pass working set fits in L2.
__device__ float g_agg_user[MAXB * D];        // seeded with h_user, edges add in
__device__ float g_agg_item[MAXB * D];        // seeded with h_item
__device__ __half g_hh_user[2 * MAXB * HP];   // fp16 h planes for edge gather
__device__ __half g_hh_item[2 * MAXB * HP];
__device__ __half g_proj_ui[2 * MAXNE * HP];  // fp16 proj planes
__device__ __half g_proj_iu[2 * MAXNE * HP];

// ---------------------------------------------------------------------------
// mma.m16n8k16 fp16 -> fp32 helper
// ---------------------------------------------------------------------------
__device__ __forceinline__ void mma_16816(float* c, unsigned a0, unsigned a1,
                                          unsigned a2, unsigned a3,
                                          unsigned b0, unsigned b1) {
    asm volatile(
        "mma.sync.aligned.m16n8k16.row.col.f32.f16.f16.f32 "
        "{%0,%1,%2,%3}, {%4,%5,%6,%7}, {%8,%9}, {%0,%1,%2,%3};"
        : "+f"(c[0]), "+f"(c[1]), "+f"(c[2]), "+f"(c[3])
        : "r"(a0), "r"(a1), "r"(a2), "r"(a3), "r"(b0), "r"(b1));
}

// split float into fp16 hi + fp16 lo residual
__device__ __forceinline__ void split_h2(float x, float y,
                                         unsigned& hi, unsigned& lo) {
    __half hx = __float2half_rn(x);
    __half hy = __float2half_rn(y);
    __half lx = __float2half_rn(x - __half2float(hx));
    __half ly = __float2half_rn(y - __half2float(hy));
    __half2 h = __halves2half2(hx, hy);
    __half2 l = __halves2half2(lx, ly);
    hi = *(unsigned*)&h;
    lo = *(unsigned*)&l;
}

// ---------------------------------------------------------------------------
// Kernel 1: h = mem[ids] @ W (warp per node, shfl broadcast).
// Writes fp32 agg seed + fp16 plane-major h tables for edge gathers.
// ---------------------------------------------------------------------------
__global__ void k_h(const float* __restrict__ mem_user,
                    const float* __restrict__ mem_item,
                    const int* __restrict__ nid_user,
                    const int* __restrict__ nid_item,
                    const float* __restrict__ Wu,
                    const float* __restrict__ Wi,
                    int B) {
    __shared__ float sWu[D * D];
    __shared__ float sWi[D * D];
    int tid = threadIdx.x;
    for (int i = tid; i < D * D; i += blockDim.x) {
        sWu[i] = Wu[i];
        sWi[i] = Wi[i];
    }
    __syncthreads();
    int lane = tid & 31;
    int warp = tid >> 5;
    int r = blockIdx.x * 8 + warp;
    if (r >= B) return;
    int nu = nid_user[r];
    int ni = nid_item[r];
    float mu = mem_user[(size_t)nu * D + lane];
    float mi = mem_item[(size_t)ni * D + lane];
    float au = 0.f, ai = 0.f;
#pragma unroll
    for (int k = 0; k < D; k++) {
        float muk = __shfl_sync(0xffffffffu, mu, k);
        float mik = __shfl_sync(0xffffffffu, mi, k);
        au += muk * sWu[k * D + lane];
        ai += mik * sWi[k * D + lane];
    }
    size_t o = (size_t)r * D + lane;
    g_agg_user[o] = au;
    g_agg_item[o] = ai;
    int plane = lane >> 4;               // 0 or 1
    int off = lane & 15;
    size_t ph = ((size_t)plane * MAXB + r) * HP + off;
    g_hh_user[ph] = __float2half_rn(au);
    g_hh_item[ph] = __float2half_rn(ai);
}

// ---------------------------------------------------------------------------
// Kernel 2: proj = feat @ We + be for BOTH edge types, tensor cores.
// Tile: 128 rows x 64 cols (cols 0..31 -> ui, 32..63 -> iu), K=64.
// Output written plane-major fp16.
// ---------------------------------------------------------------------------
__global__ void k_proj(const float* __restrict__ feat,
                       const float* __restrict__ We0, const float* __restrict__ be0,
                       const float* __restrict__ We1, const float* __restrict__ be1,
                       int NE) {
    __shared__ __half sA[128 * 72];      // feat fp16 [row][k]
    __shared__ __half sWT[64 * 72];      // [n][k]
    __shared__ float sb[64];

    int tid = threadIdx.x;
    int row0 = blockIdx.x * 128;

    for (int i = tid; i < 64 * 64; i += 256) {
        int k = i >> 6;
        int n = i & 63;
        float v = (n < 32) ? We0[k * 32 + n] : We1[k * 32 + (n - 32)];
        sWT[n * 72 + k] = __float2half_rn(v);
    }
    if (tid < 32) { sb[tid] = be0[tid]; sb[32 + tid] = be1[tid]; }

    for (int i = tid; i < 128 * 16; i += 256) {
        int r = i >> 4;
        int k0 = (i & 15) * 4;
        int gr = row0 + r;
        float4 v = make_float4(0.f, 0.f, 0.f, 0.f);
        if (gr < NE) v = *(const float4*)(feat + (size_t)gr * F + k0);
        __half2 h01 = __floats2half2_rn(v.x, v.y);
        __half2 h23 = __floats2half2_rn(v.z, v.w);
        uint2 pk;
        pk.x = *(unsigned*)&h01;
        pk.y = *(unsigned*)&h23;
        *(uint2*)(sA + r * 72 + k0) = pk;
    }
    __syncthreads();

    int lane = tid & 31;
    int warp = tid >> 5;
    int g = lane >> 2;       // 0..7
    int tig = lane & 3;      // 0..3

    const unsigned* Aw = (const unsigned*)sA;    // 36 words per row
    const unsigned* Ww = (const unsigned*)sWT;   // 36 words per n

    float acc[8][4];
#pragma unroll
    for (int t = 0; t < 8; t++) {
        float bc0 = sb[t * 8 + 2 * tig];
        float bc1 = sb[t * 8 + 2 * tig + 1];
        acc[t][0] = bc0; acc[t][1] = bc1; acc[t][2] = bc0; acc[t][3] = bc1;
    }

    int r0 = warp * 16 + g;
#pragma unroll
    for (int ks = 0; ks < 4; ks++) {
        unsigned a0 = Aw[r0 * 36 + ks * 8 + tig];
        unsigned a1 = Aw[(r0 + 8) * 36 + ks * 8 + tig];
        unsigned a2 = Aw[r0 * 36 + ks * 8 + tig + 4];
        unsigned a3 = Aw[(r0 + 8) * 36 + ks * 8 + tig + 4];
#pragma unroll
        for (int t = 0; t < 8; t++) {
            unsigned b0 = Ww[(t * 8 + g) * 36 + ks * 8 + tig];
            unsigned b1 = Ww[(t * 8 + g) * 36 + ks * 8 + tig + 4];
            mma_16816(acc[t], a0, a1, a2, a3, b0, b1);
        }
    }

    int rowA = row0 + warp * 16 + g;
    int rowB = rowA + 8;
#pragma unroll
    for (int t = 0; t < 8; t++) {
        int col = t * 8 + 2 * tig;            // even, so col & col+1 same plane
        __half2 hA = __floats2half2_rn(acc[t][0], acc[t][1]);
        __half2 hB = __floats2half2_rn(acc[t][2], acc[t][3]);
        __half* base;
        int c;
        if (col < 32) { base = g_proj_ui; c = col; }
        else          { base = g_proj_iu; c = col - 32; }
        size_t poff = (size_t)(c >> 4) * MAXNE * HP + (c & 15);
        if (rowA < NE) *(__half2*)(base + poff + (size_t)rowA * HP) = hA;
        if (rowB < NE) *(__half2*)(base + poff + (size_t)rowB * HP) = hB;
    }
}

// ---------------------------------------------------------------------------
// Kernel 3: per-edge message + scatter for ONE dim-plane (16 dims).
// ONE THREAD PER EDGE: 4 idx loads + 2x16B h + 2x16B proj + 4x red.v4
// (12 LSU ops/edge vs 36 in the lane-split version). time_w/time_b live in
// registers across a grid-stride loop. Two sequential plane launches keep
// the per-pass working set inside L2.
// ---------------------------------------------------------------------------
__global__ void k_edge(const int* __restrict__ src_ui, const int* __restrict__ dst_ui,
                       const int* __restrict__ idx_ui, const float* __restrict__ t_ui,
                       const int* __restrict__ src_iu, const int* __restrict__ dst_iu,
                       const int* __restrict__ idx_iu, const float* __restrict__ t_iu,
                       const float* __restrict__ time_w, const float* __restrict__ time_b,
                       int E, int plane) {
    // hoist time params into registers (16 + 16 floats for this plane)
    float tw[HP], tb[HP];
#pragma unroll
    for (int d = 0; d < HP; d++) {
        tw[d] = __ldg(time_w + plane * HP + d);
        tb[d] = __ldg(time_b + plane * HP + d);
    }

    long total = 2L * E;
    long stride = (long)gridDim.x * blockDim.x;
    for (long e = (long)blockIdx.x * blockDim.x + threadIdx.x; e < total; e += stride) {
        const int *srcA, *dstA, *idxA;
        const float* tA;
        const __half* hh;
        const __half* proj;
        float* agg;
        int ei;
        if (e < E) {
            ei = (int)e;
            srcA = src_ui; dstA = dst_ui; idxA = idx_ui; tA = t_ui;
            hh = g_hh_user; proj = g_proj_ui; agg = g_agg_item;
        } else {
            ei = (int)(e - E);
            srcA = src_iu; dstA = dst_iu; idxA = idx_iu; tA = t_iu;
            hh = g_hh_item; proj = g_proj_iu; agg = g_agg_user;
        }
        int srch = srcA[ei];
        int dst = dstA[ei];
        int fid = idxA[ei];
        float t = tA[ei];

        // 32B half-row gathers (two 16B loads each)
        const uint4* hp = (const uint4*)(hh + ((size_t)plane * MAXB + srch) * HP);
        uint4 hr0 = hp[0];
        uint4 hr1 = hp[1];
        const uint4* pp = (const uint4*)(proj + ((size_t)plane * MAXNE + fid) * HP);
        uint4 pr0 = pp[0];
        uint4 pr1 = pp[1];

        __half2 hv[8], pv[8];
        *(uint4*)&hv[0] = hr0; *(uint4*)&hv[4] = hr1;
        *(uint4*)&pv[0] = pr0; *(uint4*)&pv[4] = pr1;

        float msg[16];
#pragma unroll
        for (int d = 0; d < 8; d++) {
            float2 hf = __half22float2(hv[d]);
            float2 pf = __half22float2(pv[d]);
            msg[2 * d]     = hf.x + pf.x + __cosf(fmaf(t, tw[2 * d], tb[2 * d]));
            msg[2 * d + 1] = hf.y + pf.y + __cosf(fmaf(t, tw[2 * d + 1], tb[2 * d + 1]));
        }

        float* p = agg + (size_t)dst * D + plane * HP;
#pragma unroll
        for (int qq = 0; qq < 4; qq++) {
            asm volatile("red.global.add.v4.f32 [%0], {%1, %2, %3, %4};"
                         :: "l"(p + qq * 4),
                            "f"(msg[qq * 4]), "f"(msg[qq * 4 + 1]),
                            "f"(msg[qq * 4 + 2]), "f"(msg[qq * 4 + 3]) : "memory");
        }
    }
}

// ---------------------------------------------------------------------------
// Kernel 4: z = relu(agg) staged fp16 hi+lo; layer-1 GEMM on tensor cores
// (2 passes: z exact to ~2^-22); layers 2+3 scalar fp32.
// sX aliases sAlo after the MMA passes to keep smem at ~50KB.
// ---------------------------------------------------------------------------
__global__ void k_final(const float* __restrict__ W1, const float* __restrict__ b1,
                        const float* __restrict__ W2, const float* __restrict__ b2,
                        const float* __restrict__ W3, const float* __restrict__ b3,
                        float* __restrict__ out, int B) {
    __shared__ __half sA[128 * 72];    // z hi [node][k]
    __shared__ __half sAlo[128 * 72];  // z lo; reused as sX [col][node] pad 136
    __shared__ __half sW1T[64 * 72];   // [n][k]
    __shared__ float sW2[64 * 16];
    __shared__ float sW3[16];
    __shared__ float sb1[64];
    __shared__ float sb2[16];
    __shared__ float sb3;

    int tid = threadIdx.x;
    int n0 = blockIdx.x * 128;

    for (int i = tid; i < 64 * 64; i += 256) {
        int k = i >> 6;
        int n = i & 63;
        sW1T[n * 72 + k] = __float2half_rn(W1[k * 64 + n]);
    }
    for (int i = tid; i < (64 * 16) / 4; i += 256)
        ((float4*)sW2)[i] = ((const float4*)W2)[i];
    if (tid < 16) { sW3[tid] = W3[tid]; sb2[tid] = b2[tid]; }
    if (tid < 64) sb1[tid] = b1[tid];
    if (tid == 0) sb3 = b3[0];

    // stage z = relu(agg) as fp16 hi + lo
    for (int i = tid; i < 128 * 16; i += 256) {
        int n = i >> 4;
        int kc = i & 15;
        int node = n0 + n;
        float4 v = make_float4(0.f, 0.f, 0.f, 0.f);
        if (node < B) {
            v = (kc < 8) ? *(const float4*)(g_agg_user + (size_t)node * D + kc * 4)
                         : *(const float4*)(g_agg_item + (size_t)node * D + (kc - 8) * 4);
        }
        v.x = fmaxf(v.x, 0.f); v.y = fmaxf(v.y, 0.f);
        v.z = fmaxf(v.z, 0.f); v.w = fmaxf(v.w, 0.f);
        uint2 ph, pl;
        split_h2(v.x, v.y, ph.x, pl.x);
        split_h2(v.z, v.w, ph.y, pl.y);
        *(uint2*)(sA + n * 72 + kc * 4) = ph;
        *(uint2*)(sAlo + n * 72 + kc * 4) = pl;
    }
    __syncthreads();

    int lane = tid & 31;
    int warp = tid >> 5;
    int g = lane >> 2;
    int tig = lane & 3;

    const unsigned* Ww = (const unsigned*)sW1T;

    float acc[8][4];
#pragma unroll
    for (int t = 0; t < 8; t++) {
        float bc0 = sb1[t * 8 + 2 * tig];
        float bc1 = sb1[t * 8 + 2 * tig + 1];
        acc[t][0] = bc0; acc[t][1] = bc1; acc[t][2] = bc0; acc[t][3] = bc1;
    }

    int r0 = warp * 16 + g;
#pragma unroll
    for (int pass = 0; pass < 2; pass++) {
        const unsigned* Aw = (const unsigned*)(pass ? sAlo : sA);
#pragma unroll
        for (int ks = 0; ks < 4; ks++) {
            unsigned a0 = Aw[r0 * 36 + ks * 8 + tig];
            unsigned a1 = Aw[(r0 + 8) * 36 + ks * 8 + tig];
            unsigned a2 = Aw[r0 * 36 + ks * 8 + tig + 4];
            unsigned a3 = Aw[(r0 + 8) * 36 + ks * 8 + tig + 4];
#pragma unroll
            for (int t = 0; t < 8; t++) {
                unsigned b0 = Ww[(t * 8 + g) * 36 + ks * 8 + tig];
                unsigned b1 = Ww[(t * 8 + g) * 36 + ks * 8 + tig + 4];
                mma_16816(acc[t], a0, a1, a2, a3, b0, b1);
            }
        }
    }
    __syncthreads();   // all warps done reading sAlo before it becomes sX

    // x1 = relu(acc) -> sX[col][node] fp16 (aliased onto sAlo)
    __half* sX = sAlo;
    int nA = warp * 16 + g;
    int nB = nA + 8;
#pragma unroll
    for (int t = 0; t < 8; t++) {
        int col = t * 8 + 2 * tig;
        sX[col * 136 + nA] = __float2half(fmaxf(acc[t][0], 0.f));
        sX[(col + 1) * 136 + nA] = __float2half(fmaxf(acc[t][1], 0.f));
        sX[col * 136 + nB] = __float2half(fmaxf(acc[t][2], 0.f));
        sX[(col + 1) * 136 + nB] = __float2half(fmaxf(acc[t][3], 0.f));
    }
    __syncthreads();

    // layers 2+3: 2 threads per node (each 8 of the 16 mid cols)
    {
        int n = tid >> 1;
        int half = tid & 1;
        int node = n0 + n;
        float a2[8];
#pragma unroll
        for (int j = 0; j < 8; j++) a2[j] = sb2[half * 8 + j];
#pragma unroll 8
        for (int k = 0; k < 64; k++) {
            float x = __half2float(sX[k * 136 + n]);
            float4 w0 = *(const float4*)(&sW2[k * 16 + half * 8]);
            float4 w1 = *(const float4*)(&sW2[k * 16 + half * 8 + 4]);
            a2[0] += x * w0.x; a2[1] += x * w0.y; a2[2] += x * w0.z; a2[3] += x * w0.w;
            a2[4] += x * w1.x; a2[5] += x * w1.y; a2[6] += x * w1.z; a2[7] += x * w1.w;
        }
        float part = 0.f;
#pragma unroll
        for (int j = 0; j < 8; j++) part += fmaxf(a2[j], 0.f) * sW3[half * 8 + j];
        part += __shfl_xor_sync(0xffffffffu, part, 1);
        if (half == 0 && node < B) out[node] = part + sb3;
    }
}

// ---------------------------------------------------------------------------
// Launch. Detect input ordering (reference-arg order vs setup_inputs order).
// ---------------------------------------------------------------------------
extern "C" void kernel_launch(void* const* d_in, const int* in_sizes, int n_in,
                              void* d_out, int out_size) {
    bool refOrder = in_sizes[2] > 1000000;

    int iMemU, iMemI, iFeat, iTui, iTiu, iWu, iWi, iWeUI, iBeUI, iWeIU, iBeIU;
    int iTw, iTb, iW1, iB1, iW2, iB2, iW3, iB3;
    int iNidU, iNidI, iSrcUI, iDstUI, iSrcIU, iDstIU, iIdxUI, iIdxIU;

    if (refOrder) {
        iMemU = 0;  iMemI = 1;  iFeat = 2;  iTui = 3;  iTiu = 4;
        iWu = 5;    iWi = 6;    iWeUI = 7;  iBeUI = 8; iWeIU = 9; iBeIU = 10;
        iTw = 11;   iTb = 12;
        iW1 = 13;   iB1 = 14;   iW2 = 15;   iB2 = 16;  iW3 = 17;  iB3 = 18;
        iNidU = 19; iNidI = 20;
        iSrcUI = 21; iDstUI = 22; iSrcIU = 23; iDstIU = 24; iIdxUI = 25; iIdxIU = 26;
    } else {
        iMemU = 0;  iMemI = 1;  iNidU = 2;  iNidI = 3;
        iSrcUI = 4; iDstUI = 5; iSrcIU = 6; iDstIU = 7; iIdxUI = 8; iIdxIU = 9;
        iTui = 10;  iTiu = 11;  iFeat = 12;
        iWu = 13;   iWi = 14;   iWeUI = 15; iBeUI = 16; iWeIU = 17; iBeIU = 18;
        iTw = 19;   iTb = 20;
        iW1 = 21;   iB1 = 22;   iW2 = 23;   iB2 = 24;   iW3 = 25;  iB3 = 26;
    }

    const float* mem_user = (const float*)d_in[iMemU];
    const float* mem_item = (const float*)d_in[iMemI];
    const float* feat     = (const float*)d_in[iFeat];
    const float* t_ui     = (const float*)d_in[iTui];
    const float* t_iu     = (const float*)d_in[iTiu];
    const float* Wu       = (const float*)d_in[iWu];
    const float* Wi       = (const float*)d_in[iWi];
    const float* WeUI     = (const float*)d_in[iWeUI];
    const float* beUI     = (const float*)d_in[iBeUI];
    const float* WeIU     = (const float*)d_in[iWeIU];
    const float* beIU     = (const float*)d_in[iBeIU];
    const float* tw       = (const float*)d_in[iTw];
    const float* tb       = (const float*)d_in[iTb];
    const float* W1       = (const float*)d_in[iW1];
    const float* b1       = (const float*)d_in[iB1];
    const float* W2       = (const float*)d_in[iW2];
    const float* b2       = (const float*)d_in[iB2];
    const float* W3       = (const float*)d_in[iW3];
    const float* b3       = (const float*)d_in[iB3];
    const int* nid_user   = (const int*)d_in[iNidU];
    const int* nid_item   = (const int*)d_in[iNidI];
    const int* src_ui     = (const int*)d_in[iSrcUI];
    const int* dst_ui     = (const int*)d_in[iDstUI];
    const int* src_iu     = (const int*)d_in[iSrcIU];
    const int* dst_iu     = (const int*)d_in[iDstIU];
    const int* idx_ui     = (const int*)d_in[iIdxUI];
    const int* idx_iu     = (const int*)d_in[iIdxIU];

    int B  = in_sizes[iNidU];
    int E  = in_sizes[iSrcUI];
    int NE = in_sizes[iFeat] / F;

    k_h<<<(B + 7) / 8, 256>>>(mem_user, mem_item, nid_user, nid_item, Wu, Wi, B);

    k_proj<<<(NE + 127) / 128, 256>>>(feat, WeUI, beUI, WeIU, beIU, NE);

    k_edge<<<2048, 256>>>(src_ui, dst_ui, idx_ui, t_ui,
                          src_iu, dst_iu, idx_iu, t_iu,
                          tw, tb, E, 0);
    k_edge<<<2048, 256>>>(src_ui, dst_ui, idx_ui, t_ui,
                          src_iu, dst_iu, idx_iu, t_iu,
                          tw, tb, E, 1);

    k_final<<<(B + 127) / 128, 256>>>(W1, b1, W2, b2, W3, b3,
                                      (float*)d_out, B);
}

// round 12
// speedup vs baseline: 1.1179x; 1.1179x over previous
#include <cuda_runtime.h>
#include <cuda_fp16.h>
#include <math.h>

#define D 32
#define HP 16            // half-plane width (dims per edge pass)
#define F 64
#define MAXB 262144
#define MAXNE 500000

// Scratch (device globals — no allocation allowed)
// h and proj stored PLANE-MAJOR: [plane][row][16] so each edge pass gathers
// a 32B-aligned half-row and the per-pass working set fits in L2.
__device__ float g_agg_user[MAXB * D];        // seeded with h_user, edges add in
__device__ float g_agg_item[MAXB * D];        // seeded with h_item
__device__ __half g_hh_user[2 * MAXB * HP];   // fp16 h planes for edge gather
__device__ __half g_hh_item[2 * MAXB * HP];
__device__ __half g_proj_ui[2 * MAXNE * HP];  // fp16 proj planes
__device__ __half g_proj_iu[2 * MAXNE * HP];

// ---------------------------------------------------------------------------
// mma.m16n8k16 fp16 -> fp32 helper
// ---------------------------------------------------------------------------
__device__ __forceinline__ void mma_16816(float* c, unsigned a0, unsigned a1,
                                          unsigned a2, unsigned a3,
                                          unsigned b0, unsigned b1) {
    asm volatile(
        "mma.sync.aligned.m16n8k16.row.col.f32.f16.f16.f32 "
        "{%0,%1,%2,%3}, {%4,%5,%6,%7}, {%8,%9}, {%0,%1,%2,%3};"
        : "+f"(c[0]), "+f"(c[1]), "+f"(c[2]), "+f"(c[3])
        : "r"(a0), "r"(a1), "r"(a2), "r"(a3), "r"(b0), "r"(b1));
}

// split float into fp16 hi + fp16 lo residual
__device__ __forceinline__ void split_h2(float x, float y,
                                         unsigned& hi, unsigned& lo) {
    __half hx = __float2half_rn(x);
    __half hy = __float2half_rn(y);
    __half lx = __float2half_rn(x - __half2float(hx));
    __half ly = __float2half_rn(y - __half2float(hy));
    __half2 h = __halves2half2(hx, hy);
    __half2 l = __halves2half2(lx, ly);
    hi = *(unsigned*)&h;
    lo = *(unsigned*)&l;
}

// ---------------------------------------------------------------------------
// Kernel 1: h = mem[ids] @ W (warp per node, shfl broadcast).
// Writes fp32 agg seed + fp16 plane-major h tables for edge gathers.
// ---------------------------------------------------------------------------
__global__ void k_h(const float* __restrict__ mem_user,
                    const float* __restrict__ mem_item,
                    const int* __restrict__ nid_user,
                    const int* __restrict__ nid_item,
                    const float* __restrict__ Wu,
                    const float* __restrict__ Wi,
                    int B) {
    __shared__ float sWu[D * D];
    __shared__ float sWi[D * D];
    int tid = threadIdx.x;
    for (int i = tid; i < D * D; i += blockDim.x) {
        sWu[i] = Wu[i];
        sWi[i] = Wi[i];
    }
    __syncthreads();
    int lane = tid & 31;
    int warp = tid >> 5;
    int r = blockIdx.x * 8 + warp;
    if (r >= B) return;
    int nu = nid_user[r];
    int ni = nid_item[r];
    float mu = mem_user[(size_t)nu * D + lane];
    float mi = mem_item[(size_t)ni * D + lane];
    float au = 0.f, ai = 0.f;
#pragma unroll
    for (int k = 0; k < D; k++) {
        float muk = __shfl_sync(0xffffffffu, mu, k);
        float mik = __shfl_sync(0xffffffffu, mi, k);
        au += muk * sWu[k * D + lane];
        ai += mik * sWi[k * D + lane];
    }
    size_t o = (size_t)r * D + lane;
    g_agg_user[o] = au;
    g_agg_item[o] = ai;
    int plane = lane >> 4;               // 0 or 1
    int off = lane & 15;
    size_t ph = ((size_t)plane * MAXB + r) * HP + off;
    g_hh_user[ph] = __float2half_rn(au);
    g_hh_item[ph] = __float2half_rn(ai);
}

// ---------------------------------------------------------------------------
// Kernel 2: proj = feat @ We + be for BOTH edge types, tensor cores.
// Tile: 128 rows x 64 cols (cols 0..31 -> ui, 32..63 -> iu), K=64.
// Epilogue: stage fp16 result tile in smem (reusing sA), then write out
// plane-major with fully coalesced 16B uint4 stores.
// ---------------------------------------------------------------------------
__global__ void k_proj(const float* __restrict__ feat,
                       const float* __restrict__ We0, const float* __restrict__ be0,
                       const float* __restrict__ We1, const float* __restrict__ be1,
                       int NE) {
    __shared__ __half sA[128 * 72];      // feat fp16 [row][k]; reused as out tile
    __shared__ __half sWT[64 * 72];      // [n][k]
    __shared__ float sb[64];

    int tid = threadIdx.x;
    int row0 = blockIdx.x * 128;

    for (int i = tid; i < 64 * 64; i += 256) {
        int k = i >> 6;
        int n = i & 63;
        float v = (n < 32) ? We0[k * 32 + n] : We1[k * 32 + (n - 32)];
        sWT[n * 72 + k] = __float2half_rn(v);
    }
    if (tid < 32) { sb[tid] = be0[tid]; sb[32 + tid] = be1[tid]; }

    for (int i = tid; i < 128 * 16; i += 256) {
        int r = i >> 4;
        int k0 = (i & 15) * 4;
        int gr = row0 + r;
        float4 v = make_float4(0.f, 0.f, 0.f, 0.f);
        if (gr < NE) v = *(const float4*)(feat + (size_t)gr * F + k0);
        __half2 h01 = __floats2half2_rn(v.x, v.y);
        __half2 h23 = __floats2half2_rn(v.z, v.w);
        uint2 pk;
        pk.x = *(unsigned*)&h01;
        pk.y = *(unsigned*)&h23;
        *(uint2*)(sA + r * 72 + k0) = pk;
    }
    __syncthreads();

    int lane = tid & 31;
    int warp = tid >> 5;
    int g = lane >> 2;       // 0..7
    int tig = lane & 3;      // 0..3

    const unsigned* Aw = (const unsigned*)sA;    // 36 words per row
    const unsigned* Ww = (const unsigned*)sWT;   // 36 words per n

    float acc[8][4];
#pragma unroll
    for (int t = 0; t < 8; t++) {
        float bc0 = sb[t * 8 + 2 * tig];
        float bc1 = sb[t * 8 + 2 * tig + 1];
        acc[t][0] = bc0; acc[t][1] = bc1; acc[t][2] = bc0; acc[t][3] = bc1;
    }

    int r0 = warp * 16 + g;
#pragma unroll
    for (int ks = 0; ks < 4; ks++) {
        unsigned a0 = Aw[r0 * 36 + ks * 8 + tig];
        unsigned a1 = Aw[(r0 + 8) * 36 + ks * 8 + tig];
        unsigned a2 = Aw[r0 * 36 + ks * 8 + tig + 4];
        unsigned a3 = Aw[(r0 + 8) * 36 + ks * 8 + tig + 4];
#pragma unroll
        for (int t = 0; t < 8; t++) {
            unsigned b0 = Ww[(t * 8 + g) * 36 + ks * 8 + tig];
            unsigned b1 = Ww[(t * 8 + g) * 36 + ks * 8 + tig + 4];
            mma_16816(acc[t], a0, a1, a2, a3, b0, b1);
        }
    }
    __syncthreads();   // everyone done reading sA before it becomes the out tile

    // stage result tile in smem: sA[row][col] fp16, stride 72
    int rA = warp * 16 + g;
    int rB = rA + 8;
#pragma unroll
    for (int t = 0; t < 8; t++) {
        int col = t * 8 + 2 * tig;   // even -> 4B aligned
        *(__half2*)(sA + rA * 72 + col) = __floats2half2_rn(acc[t][0], acc[t][1]);
        *(__half2*)(sA + rB * 72 + col) = __floats2half2_rn(acc[t][2], acc[t][3]);
    }
    __syncthreads();

    // coalesced writeout: 1024 16B-chunks (128 rows x 2 types x 2 planes x 2)
    for (int i = tid; i < 1024; i += 256) {
        int r = i & 127;             // row within tile
        int c8 = i >> 7;             // 0..7 : which 8-half chunk
        int col = c8 * 8;            // source col in tile (0..56)
        int gr = row0 + r;
        if (gr >= NE) continue;
        uint4 v = *(const uint4*)(sA + r * 72 + col);   // 16B-aligned (144*r+2*col)
        __half* base = (col < 32) ? g_proj_ui : g_proj_iu;
        int c = col & 31;            // col within type
        int plane = c >> 4;          // 0 or 1
        int off = c & 15;            // 0 or 8
        *(uint4*)(base + ((size_t)plane * MAXNE + gr) * HP + off) = v;
    }
}

// ---------------------------------------------------------------------------
// Kernel 3: per-edge message + scatter for ONE dim-plane (16 dims).
// 4 lanes per edge, lane handles 4 dims -> one red.global.add.v4.f32.
// Launched twice (plane 0, plane 1) SEQUENTIALLY so the per-pass working
// set (h half + proj half + agg half ~= 80MB) fits in L2.
// ---------------------------------------------------------------------------
__global__ void k_edge(const int* __restrict__ src_ui, const int* __restrict__ dst_ui,
                       const int* __restrict__ idx_ui, const float* __restrict__ t_ui,
                       const int* __restrict__ src_iu, const int* __restrict__ dst_iu,
                       const int* __restrict__ idx_iu, const float* __restrict__ t_iu,
                       const float* __restrict__ time_w, const float* __restrict__ time_b,
                       int E, int plane) {
    int tid = threadIdx.x;
    int lane = tid & 31;
    int warp = tid >> 5;
    int q = lane & 3;        // dim quad within the 16-dim plane
    int s = lane >> 2;       // edge slot within warp (0..7)
    long e = (long)blockIdx.x * 64 + warp * 8 + s;
    if (e >= 2L * E) return;

    const int *srcA, *dstA, *idxA;
    const float* tA;
    const __half* hh;
    const __half* proj;
    float* agg;
    int ei;
    if (e < E) {
        ei = (int)e;
        srcA = src_ui; dstA = dst_ui; idxA = idx_ui; tA = t_ui;
        hh = g_hh_user; proj = g_proj_ui; agg = g_agg_item;
    } else {
        ei = (int)(e - E);
        srcA = src_iu; dstA = dst_iu; idxA = idx_iu; tA = t_iu;
        hh = g_hh_item; proj = g_proj_iu; agg = g_agg_user;
    }
    int srch = srcA[ei];
    int dst = dstA[ei];
    int fid = idxA[ei];
    float t = tA[ei];

    const __half2* hp = (const __half2*)(hh + ((size_t)plane * MAXB + srch) * HP + q * 4);
    float2 h01 = __half22float2(hp[0]);
    float2 h23 = __half22float2(hp[1]);
    const __half2* pp = (const __half2*)(proj + ((size_t)plane * MAXNE + fid) * HP + q * 4);
    float2 p01 = __half22float2(pp[0]);
    float2 p23 = __half22float2(pp[1]);
    int dq = plane * HP + q * 4;
    float4 tw = *(const float4*)(time_w + dq);
    float4 tb = *(const float4*)(time_b + dq);

    float m0 = h01.x + p01.x + __cosf(fmaf(t, tw.x, tb.x));
    float m1 = h01.y + p01.y + __cosf(fmaf(t, tw.y, tb.y));
    float m2 = h23.x + p23.x + __cosf(fmaf(t, tw.z, tb.z));
    float m3 = h23.y + p23.y + __cosf(fmaf(t, tw.w, tb.w));

    float* p = agg + (size_t)dst * D + dq;
    asm volatile("red.global.add.v4.f32 [%0], {%1, %2, %3, %4};"
                 :: "l"(p), "f"(m0), "f"(m1), "f"(m2), "f"(m3) : "memory");
}

// ---------------------------------------------------------------------------
// Kernel 4: z = relu(agg) staged fp16 hi+lo; layer-1 GEMM on tensor cores
// (2 passes: z exact to ~2^-22); layers 2+3 scalar fp32.
// sX aliases sAlo after the MMA passes to keep smem at ~50KB.
// ---------------------------------------------------------------------------
__global__ void k_final(const float* __restrict__ W1, const float* __restrict__ b1,
                        const float* __restrict__ W2, const float* __restrict__ b2,
                        const float* __restrict__ W3, const float* __restrict__ b3,
                        float* __restrict__ out, int B) {
    __shared__ __half sA[128 * 72];    // z hi [node][k]
    __shared__ __half sAlo[128 * 72];  // z lo; reused as sX [col][node] pad 136
    __shared__ __half sW1T[64 * 72];   // [n][k]
    __shared__ float sW2[64 * 16];
    __shared__ float sW3[16];
    __shared__ float sb1[64];
    __shared__ float sb2[16];
    __shared__ float sb3;

    int tid = threadIdx.x;
    int n0 = blockIdx.x * 128;

    for (int i = tid; i < 64 * 64; i += 256) {
        int k = i >> 6;
        int n = i & 63;
        sW1T[n * 72 + k] = __float2half_rn(W1[k * 64 + n]);
    }
    for (int i = tid; i < (64 * 16) / 4; i += 256)
        ((float4*)sW2)[i] = ((const float4*)W2)[i];
    if (tid < 16) { sW3[tid] = W3[tid]; sb2[tid] = b2[tid]; }
    if (tid < 64) sb1[tid] = b1[tid];
    if (tid == 0) sb3 = b3[0];

    // stage z = relu(agg) as fp16 hi + lo
    for (int i = tid; i < 128 * 16; i += 256) {
        int n = i >> 4;
        int kc = i & 15;
        int node = n0 + n;
        float4 v = make_float4(0.f, 0.f, 0.f, 0.f);
        if (node < B) {
            v = (kc < 8) ? *(const float4*)(g_agg_user + (size_t)node * D + kc * 4)
                         : *(const float4*)(g_agg_item + (size_t)node * D + (kc - 8) * 4);
        }
        v.x = fmaxf(v.x, 0.f); v.y = fmaxf(v.y, 0.f);
        v.z = fmaxf(v.z, 0.f); v.w = fmaxf(v.w, 0.f);
        uint2 ph, pl;
        split_h2(v.x, v.y, ph.x, pl.x);
        split_h2(v.z, v.w, ph.y, pl.y);
        *(uint2*)(sA + n * 72 + kc * 4) = ph;
        *(uint2*)(sAlo + n * 72 + kc * 4) = pl;
    }
    __syncthreads();

    int lane = tid & 31;
    int warp = tid >> 5;
    int g = lane >> 2;
    int tig = lane & 3;

    const unsigned* Ww = (const unsigned*)sW1T;

    float acc[8][4];
#pragma unroll
    for (int t = 0; t < 8; t++) {
        float bc0 = sb1[t * 8 + 2 * tig];
        float bc1 = sb1[t * 8 + 2 * tig + 1];
        acc[t][0] = bc0; acc[t][1] = bc1; acc[t][2] = bc0; acc[t][3] = bc1;
    }

    int r0 = warp * 16 + g;
#pragma unroll
    for (int pass = 0; pass < 2; pass++) {
        const unsigned* Aw = (const unsigned*)(pass ? sAlo : sA);
#pragma unroll
        for (int ks = 0; ks < 4; ks++) {
            unsigned a0 = Aw[r0 * 36 + ks * 8 + tig];
            unsigned a1 = Aw[(r0 + 8) * 36 + ks * 8 + tig];
            unsigned a2 = Aw[r0 * 36 + ks * 8 + tig + 4];
            unsigned a3 = Aw[(r0 + 8) * 36 + ks * 8 + tig + 4];
#pragma unroll
            for (int t = 0; t < 8; t++) {
                unsigned b0 = Ww[(t * 8 + g) * 36 + ks * 8 + tig];
                unsigned b1 = Ww[(t * 8 + g) * 36 + ks * 8 + tig + 4];
                mma_16816(acc[t], a0, a1, a2, a3, b0, b1);
            }
        }
    }
    __syncthreads();   // all warps done reading sAlo before it becomes sX

    // x1 = relu(acc) -> sX[col][node] fp16 (aliased onto sAlo)
    __half* sX = sAlo;
    int nA = warp * 16 + g;
    int nB = nA + 8;
#pragma unroll
    for (int t = 0; t < 8; t++) {
        int col = t * 8 + 2 * tig;
        sX[col * 136 + nA] = __float2half(fmaxf(acc[t][0], 0.f));
        sX[(col + 1) * 136 + nA] = __float2half(fmaxf(acc[t][1], 0.f));
        sX[col * 136 + nB] = __float2half(fmaxf(acc[t][2], 0.f));
        sX[(col + 1) * 136 + nB] = __float2half(fmaxf(acc[t][3], 0.f));
    }
    __syncthreads();

    // layers 2+3: 2 threads per node (each 8 of the 16 mid cols)
    {
        int n = tid >> 1;
        int half = tid & 1;
        int node = n0 + n;
        float a2[8];
#pragma unroll
        for (int j = 0; j < 8; j++) a2[j] = sb2[half * 8 + j];
#pragma unroll 8
        for (int k = 0; k < 64; k++) {
            float x = __half2float(sX[k * 136 + n]);
            float4 w0 = *(const float4*)(&sW2[k * 16 + half * 8]);
            float4 w1 = *(const float4*)(&sW2[k * 16 + half * 8 + 4]);
            a2[0] += x * w0.x; a2[1] += x * w0.y; a2[2] += x * w0.z; a2[3] += x * w0.w;
            a2[4] += x * w1.x; a2[5] += x * w1.y; a2[6] += x * w1.z; a2[7] += x * w1.w;
        }
        float part = 0.f;
#pragma unroll
        for (int j = 0; j < 8; j++) part += fmaxf(a2[j], 0.f) * sW3[half * 8 + j];
        part += __shfl_xor_sync(0xffffffffu, part, 1);
        if (half == 0 && node < B) out[node] = part + sb3;
    }
}

// ---------------------------------------------------------------------------
// Launch. Detect input ordering (reference-arg order vs setup_inputs order).
// ---------------------------------------------------------------------------
extern "C" void kernel_launch(void* const* d_in, const int* in_sizes, int n_in,
                              void* d_out, int out_size) {
    bool refOrder = in_sizes[2] > 1000000;

    int iMemU, iMemI, iFeat, iTui, iTiu, iWu, iWi, iWeUI, iBeUI, iWeIU, iBeIU;
    int iTw, iTb, iW1, iB1, iW2, iB2, iW3, iB3;
    int iNidU, iNidI, iSrcUI, iDstUI, iSrcIU, iDstIU, iIdxUI, iIdxIU;

    if (refOrder) {
        iMemU = 0;  iMemI = 1;  iFeat = 2;  iTui = 3;  iTiu = 4;
        iWu = 5;    iWi = 6;    iWeUI = 7;  iBeUI = 8; iWeIU = 9; iBeIU = 10;
        iTw = 11;   iTb = 12;
        iW1 = 13;   iB1 = 14;   iW2 = 15;   iB2 = 16;  iW3 = 17;  iB3 = 18;
        iNidU = 19; iNidI = 20;
        iSrcUI = 21; iDstUI = 22; iSrcIU = 23; iDstIU = 24; iIdxUI = 25; iIdxIU = 26;
    } else {
        iMemU = 0;  iMemI = 1;  iNidU = 2;  iNidI = 3;
        iSrcUI = 4; iDstUI = 5; iSrcIU = 6; iDstIU = 7; iIdxUI = 8; iIdxIU = 9;
        iTui = 10;  iTiu = 11;  iFeat = 12;
        iWu = 13;   iWi = 14;   iWeUI = 15; iBeUI = 16; iWeIU = 17; iBeIU = 18;
        iTw = 19;   iTb = 20;
        iW1 = 21;   iB1 = 22;   iW2 = 23;   iB2 = 24;   iW3 = 25;  iB3 = 26;
    }

    const float* mem_user = (const float*)d_in[iMemU];
    const float* mem_item = (const float*)d_in[iMemI];
    const float* feat     = (const float*)d_in[iFeat];
    const float* t_ui     = (const float*)d_in[iTui];
    const float* t_iu     = (const float*)d_in[iTiu];
    const float* Wu       = (const float*)d_in[iWu];
    const float* Wi       = (const float*)d_in[iWi];
    const float* WeUI     = (const float*)d_in[iWeUI];
    const float* beUI     = (const float*)d_in[iBeUI];
    const float* WeIU     = (const float*)d_in[iWeIU];
    const float* beIU     = (const float*)d_in[iBeIU];
    const float* tw       = (const float*)d_in[iTw];
    const float* tb       = (const float*)d_in[iTb];
    const float* W1       = (const float*)d_in[iW1];
    const float* b1       = (const float*)d_in[iB1];
    const float* W2       = (const float*)d_in[iW2];
    const float* b2       = (const float*)d_in[iB2];
    const float* W3       = (const float*)d_in[iW3];
    const float* b3       = (const float*)d_in[iB3];
    const int* nid_user   = (const int*)d_in[iNidU];
    const int* nid_item   = (const int*)d_in[iNidI];
    const int* src_ui     = (const int*)d_in[iSrcUI];
    const int* dst_ui     = (const int*)d_in[iDstUI];
    const int* src_iu     = (const int*)d_in[iSrcIU];
    const int* dst_iu     = (const int*)d_in[iDstIU];
    const int* idx_ui     = (const int*)d_in[iIdxUI];
    const int* idx_iu     = (const int*)d_in[iIdxIU];

    int B  = in_sizes[iNidU];
    int E  = in_sizes[iSrcUI];
    int NE = in_sizes[iFeat] / F;

    k_h<<<(B + 7) / 8, 256>>>(mem_user, mem_item, nid_user, nid_item, Wu, Wi, B);

    k_proj<<<(NE + 127) / 128, 256>>>(feat, WeUI, beUI, WeIU, beIU, NE);

    long total_edges = 2L * E;
    int nb_e = (int)((total_edges + 63) / 64);
    k_edge<<<nb_e, 256>>>(src_ui, dst_ui, idx_ui, t_ui,
                          src_iu, dst_iu, idx_iu, t_iu,
                          tw, tb, E, 0);
    k_edge<<<nb_e, 256>>>(src_ui, dst_ui, idx_ui, t_ui,
                          src_iu, dst_iu, idx_iu, t_iu,
                          tw, tb, E, 1);

    k_final<<<(B + 127) / 128, 256>>>(W1, b1, W2, b2, W3, b3,
                                      (float*)d_out, B);
}

// round 13
// speedup vs baseline: 1.3522x; 1.2096x over previous
#include <cuda_runtime.h>
#include <cuda_fp16.h>
#include <math.h>

#define D 32
#define HP 16            // half-plane width (dims per edge pass)
#define F 64
#define MAXB 262144
#define MAXNE 500000

// Scratch (device globals — no allocation allowed)
// h and proj stored PLANE-MAJOR: [plane][row][16] so each edge pass gathers
// a 32B-aligned half-row and the per-pass working set fits in L2.
__device__ float g_agg_user[MAXB * D];        // seeded with h_user, edges add in
__device__ float g_agg_item[MAXB * D];        // seeded with h_item
__device__ __half g_hh_user[2 * MAXB * HP];   // fp16 h planes for edge gather
__device__ __half g_hh_item[2 * MAXB * HP];
__device__ __half g_proj_ui[2 * MAXNE * HP];  // fp16 proj planes
__device__ __half g_proj_iu[2 * MAXNE * HP];

// ---------------------------------------------------------------------------
// mma.m16n8k16 fp16 -> fp32 helper
// ---------------------------------------------------------------------------
__device__ __forceinline__ void mma_16816(float* c, unsigned a0, unsigned a1,
                                          unsigned a2, unsigned a3,
                                          unsigned b0, unsigned b1) {
    asm volatile(
        "mma.sync.aligned.m16n8k16.row.col.f32.f16.f16.f32 "
        "{%0,%1,%2,%3}, {%4,%5,%6,%7}, {%8,%9}, {%0,%1,%2,%3};"
        : "+f"(c[0]), "+f"(c[1]), "+f"(c[2]), "+f"(c[3])
        : "r"(a0), "r"(a1), "r"(a2), "r"(a3), "r"(b0), "r"(b1));
}

// split float into fp16 hi + fp16 lo residual
__device__ __forceinline__ void split_h2(float x, float y,
                                         unsigned& hi, unsigned& lo) {
    __half hx = __float2half_rn(x);
    __half hy = __float2half_rn(y);
    __half lx = __float2half_rn(x - __half2float(hx));
    __half ly = __float2half_rn(y - __half2float(hy));
    __half2 h = __halves2half2(hx, hy);
    __half2 l = __halves2half2(lx, ly);
    hi = *(unsigned*)&h;
    lo = *(unsigned*)&l;
}

// ---------------------------------------------------------------------------
// Kernel 1: h = mem[ids] @ W on TENSOR CORES (3-pass hi/lo: exact to ~2^-21).
// Block = 256 threads handles 256 nodes; user then item phase (smem reused).
// Writes fp32 agg seed + fp16 plane-major h tables. No shfl anywhere.
// smem strides: 40 halfs (20 uints) -> conflict-free frag reads.
// ---------------------------------------------------------------------------
__global__ void k_h(const float* __restrict__ mem_user,
                    const float* __restrict__ mem_item,
                    const int* __restrict__ nid_user,
                    const int* __restrict__ nid_item,
                    const float* __restrict__ Wu,
                    const float* __restrict__ Wi,
                    int B) {
    __shared__ __half sM[256 * 40];     // gathered mem rows, fp16 hi
    __shared__ __half sMlo[256 * 40];   // fp16 lo residual
    __shared__ __half sWT[32 * 40];     // W^T [n][k] hi (one type at a time)
    __shared__ __half sWTlo[32 * 40];   // W^T lo
    __shared__ int sIds[512];           // user ids [0..255], item ids [256..511]

    int tid = threadIdx.x;
    int n0 = blockIdx.x * 256;
    int lane = tid & 31;
    int warp = tid >> 5;
    int g = lane >> 2;
    int tig = lane & 3;

    // stage both id arrays
    {
        int node = n0 + tid;
        sIds[tid] = (node < B) ? nid_user[node] : 0;
        sIds[256 + tid] = (node < B) ? nid_item[node] : 0;
    }

    for (int type = 0; type < 2; type++) {
        const float* mem = type ? mem_item : mem_user;
        const float* W = type ? Wi : Wu;
        float* agg = type ? g_agg_item : g_agg_user;
        __half* hh = type ? g_hh_item : g_hh_user;

        __syncthreads();   // ids ready (iter0) / prev mma done reading smem

        // stage W^T hi/lo: sWT[n*40+k] = W[k*32+n]
        for (int i = tid; i < 32 * 32; i += 256) {
            int k = i >> 5;
            int n = i & 31;
            float v = W[k * 32 + n];
            __half hi = __float2half_rn(v);
            sWT[n * 40 + k] = hi;
            sWTlo[n * 40 + k] = __float2half_rn(v - __half2float(hi));
        }

        // gather 256 mem rows (8 float4-chunks each) as fp16 hi/lo
        for (int it = 0; it < 8; it++) {
            int idx = tid + it * 256;
            int row = idx >> 3;
            int c = idx & 7;
            int nid = sIds[type * 256 + row];
            float4 v = *(const float4*)(mem + (size_t)nid * D + c * 4);
            uint2 ph, pl;
            split_h2(v.x, v.y, ph.x, pl.x);
            split_h2(v.z, v.w, ph.y, pl.y);
            *(uint2*)(sM + row * 40 + c * 4) = ph;
            *(uint2*)(sMlo + row * 40 + c * 4) = pl;
        }
        __syncthreads();

        // mma: warp covers rows [warp*32, warp*32+32); 2 mtiles x 4 ntiles
        float acc[2][4][4];
#pragma unroll
        for (int m = 0; m < 2; m++)
#pragma unroll
            for (int nt = 0; nt < 4; nt++)
#pragma unroll
                for (int j = 0; j < 4; j++) acc[m][nt][j] = 0.f;

#pragma unroll
        for (int pass = 0; pass < 3; pass++) {
            const unsigned* Aw = (const unsigned*)(pass == 1 ? sMlo : sM);
            const unsigned* Ww = (const unsigned*)(pass == 2 ? sWTlo : sWT);
#pragma unroll
            for (int m = 0; m < 2; m++) {
                int rb = warp * 32 + m * 16 + g;
#pragma unroll
                for (int ks = 0; ks < 2; ks++) {
                    unsigned a0 = Aw[rb * 20 + ks * 8 + tig];
                    unsigned a1 = Aw[(rb + 8) * 20 + ks * 8 + tig];
                    unsigned a2 = Aw[rb * 20 + ks * 8 + tig + 4];
                    unsigned a3 = Aw[(rb + 8) * 20 + ks * 8 + tig + 4];
#pragma unroll
                    for (int nt = 0; nt < 4; nt++) {
                        unsigned b0 = Ww[(nt * 8 + g) * 20 + ks * 8 + tig];
                        unsigned b1 = Ww[(nt * 8 + g) * 20 + ks * 8 + tig + 4];
                        mma_16816(acc[m][nt], a0, a1, a2, a3, b0, b1);
                    }
                }
            }
        }

        // epilogue: agg (fp32) + hh (fp16 plane-major)
#pragma unroll
        for (int m = 0; m < 2; m++) {
            int rA = warp * 32 + m * 16 + g;
            int rB = rA + 8;
            int nodeA = n0 + rA;
            int nodeB = n0 + rB;
#pragma unroll
            for (int nt = 0; nt < 4; nt++) {
                int col = nt * 8 + 2 * tig;      // even
                int plane = col >> 4;
                int off = col & 15;
                float c0 = acc[m][nt][0], c1 = acc[m][nt][1];
                float c2 = acc[m][nt][2], c3 = acc[m][nt][3];
                if (nodeA < B) {
                    *(float2*)(agg + (size_t)nodeA * D + col) = make_float2(c0, c1);
                    *(__half2*)(hh + ((size_t)plane * MAXB + nodeA) * HP + off) =
                        __floats2half2_rn(c0, c1);
                }
                if (nodeB < B) {
                    *(float2*)(agg + (size_t)nodeB * D + col) = make_float2(c2, c3);
                    *(__half2*)(hh + ((size_t)plane * MAXB + nodeB) * HP + off) =
                        __floats2half2_rn(c2, c3);
                }
            }
        }
    }
}

// ---------------------------------------------------------------------------
// Kernel 2: proj = feat @ We + be for BOTH edge types, tensor cores.
// Tile: 128 rows x 64 cols (cols 0..31 -> ui, 32..63 -> iu), K=64.
// Epilogue: stage fp16 tile in smem, coalesced 16B plane-major writeout.
// ---------------------------------------------------------------------------
__global__ void k_proj(const float* __restrict__ feat,
                       const float* __restrict__ We0, const float* __restrict__ be0,
                       const float* __restrict__ We1, const float* __restrict__ be1,
                       int NE) {
    __shared__ __half sA[128 * 72];      // feat fp16 [row][k]; reused as out tile
    __shared__ __half sWT[64 * 72];      // [n][k]
    __shared__ float sb[64];

    int tid = threadIdx.x;
    int row0 = blockIdx.x * 128;

    for (int i = tid; i < 64 * 64; i += 256) {
        int k = i >> 6;
        int n = i & 63;
        float v = (n < 32) ? We0[k * 32 + n] : We1[k * 32 + (n - 32)];
        sWT[n * 72 + k] = __float2half_rn(v);
    }
    if (tid < 32) { sb[tid] = be0[tid]; sb[32 + tid] = be1[tid]; }

    for (int i = tid; i < 128 * 16; i += 256) {
        int r = i >> 4;
        int k0 = (i & 15) * 4;
        int gr = row0 + r;
        float4 v = make_float4(0.f, 0.f, 0.f, 0.f);
        if (gr < NE) v = *(const float4*)(feat + (size_t)gr * F + k0);
        __half2 h01 = __floats2half2_rn(v.x, v.y);
        __half2 h23 = __floats2half2_rn(v.z, v.w);
        uint2 pk;
        pk.x = *(unsigned*)&h01;
        pk.y = *(unsigned*)&h23;
        *(uint2*)(sA + r * 72 + k0) = pk;
    }
    __syncthreads();

    int lane = tid & 31;
    int warp = tid >> 5;
    int g = lane >> 2;       // 0..7
    int tig = lane & 3;      // 0..3

    const unsigned* Aw = (const unsigned*)sA;    // 36 words per row
    const unsigned* Ww = (const unsigned*)sWT;   // 36 words per n

    float acc[8][4];
#pragma unroll
    for (int t = 0; t < 8; t++) {
        float bc0 = sb[t * 8 + 2 * tig];
        float bc1 = sb[t * 8 + 2 * tig + 1];
        acc[t][0] = bc0; acc[t][1] = bc1; acc[t][2] = bc0; acc[t][3] = bc1;
    }

    int r0 = warp * 16 + g;
#pragma unroll
    for (int ks = 0; ks < 4; ks++) {
        unsigned a0 = Aw[r0 * 36 + ks * 8 + tig];
        unsigned a1 = Aw[(r0 + 8) * 36 + ks * 8 + tig];
        unsigned a2 = Aw[r0 * 36 + ks * 8 + tig + 4];
        unsigned a3 = Aw[(r0 + 8) * 36 + ks * 8 + tig + 4];
#pragma unroll
        for (int t = 0; t < 8; t++) {
            unsigned b0 = Ww[(t * 8 + g) * 36 + ks * 8 + tig];
            unsigned b1 = Ww[(t * 8 + g) * 36 + ks * 8 + tig + 4];
            mma_16816(acc[t], a0, a1, a2, a3, b0, b1);
        }
    }
    __syncthreads();   // everyone done reading sA before it becomes the out tile

    // stage result tile in smem: sA[row][col] fp16, stride 72
    int rA = warp * 16 + g;
    int rB = rA + 8;
#pragma unroll
    for (int t = 0; t < 8; t++) {
        int col = t * 8 + 2 * tig;   // even -> 4B aligned
        *(__half2*)(sA + rA * 72 + col) = __floats2half2_rn(acc[t][0], acc[t][1]);
        *(__half2*)(sA + rB * 72 + col) = __floats2half2_rn(acc[t][2], acc[t][3]);
    }
    __syncthreads();

    // coalesced writeout: 1024 16B-chunks (128 rows x 2 types x 2 planes x 2)
    for (int i = tid; i < 1024; i += 256) {
        int r = i & 127;             // row within tile
        int c8 = i >> 7;             // 0..7 : which 8-half chunk
        int col = c8 * 8;            // source col in tile (0..56)
        int gr = row0 + r;
        if (gr >= NE) continue;
        uint4 v = *(const uint4*)(sA + r * 72 + col);   // 16B-aligned (144*r+2*col)
        __half* base = (col < 32) ? g_proj_ui : g_proj_iu;
        int c = col & 31;            // col within type
        int plane = c >> 4;          // 0 or 1
        int off = c & 15;            // 0 or 8
        *(uint4*)(base + ((size_t)plane * MAXNE + gr) * HP + off) = v;
    }
}

// ---------------------------------------------------------------------------
// Kernel 3: per-edge message + scatter for ONE dim-plane (16 dims).
// 4 lanes per edge, lane handles 4 dims -> one red.global.add.v4.f32.
// Launched twice (plane 0, plane 1) SEQUENTIALLY so the per-pass working
// set (h half + proj half + agg half ~= 80MB) fits in L2.
// ---------------------------------------------------------------------------
__global__ void k_edge(const int* __restrict__ src_ui, const int* __restrict__ dst_ui,
                       const int* __restrict__ idx_ui, const float* __restrict__ t_ui,
                       const int* __restrict__ src_iu, const int* __restrict__ dst_iu,
                       const int* __restrict__ idx_iu, const float* __restrict__ t_iu,
                       const float* __restrict__ time_w, const float* __restrict__ time_b,
                       int E, int plane) {
    int tid = threadIdx.x;
    int lane = tid & 31;
    int warp = tid >> 5;
    int q = lane & 3;        // dim quad within the 16-dim plane
    int s = lane >> 2;       // edge slot within warp (0..7)
    long e = (long)blockIdx.x * 64 + warp * 8 + s;
    if (e >= 2L * E) return;

    const int *srcA, *dstA, *idxA;
    const float* tA;
    const __half* hh;
    const __half* proj;
    float* agg;
    int ei;
    if (e < E) {
        ei = (int)e;
        srcA = src_ui; dstA = dst_ui; idxA = idx_ui; tA = t_ui;
        hh = g_hh_user; proj = g_proj_ui; agg = g_agg_item;
    } else {
        ei = (int)(e - E);
        srcA = src_iu; dstA = dst_iu; idxA = idx_iu; tA = t_iu;
        hh = g_hh_item; proj = g_proj_iu; agg = g_agg_user;
    }
    int srch = srcA[ei];
    int dst = dstA[ei];
    int fid = idxA[ei];
    float t = tA[ei];

    const __half2* hp = (const __half2*)(hh + ((size_t)plane * MAXB + srch) * HP + q * 4);
    float2 h01 = __half22float2(hp[0]);
    float2 h23 = __half22float2(hp[1]);
    const __half2* pp = (const __half2*)(proj + ((size_t)plane * MAXNE + fid) * HP + q * 4);
    float2 p01 = __half22float2(pp[0]);
    float2 p23 = __half22float2(pp[1]);
    int dq = plane * HP + q * 4;
    float4 tw = *(const float4*)(time_w + dq);
    float4 tb = *(const float4*)(time_b + dq);

    float m0 = h01.x + p01.x + __cosf(fmaf(t, tw.x, tb.x));
    float m1 = h01.y + p01.y + __cosf(fmaf(t, tw.y, tb.y));
    float m2 = h23.x + p23.x + __cosf(fmaf(t, tw.z, tb.z));
    float m3 = h23.y + p23.y + __cosf(fmaf(t, tw.w, tb.w));

    float* p = agg + (size_t)dst * D + dq;
    asm volatile("red.global.add.v4.f32 [%0], {%1, %2, %3, %4};"
                 :: "l"(p), "f"(m0), "f"(m1), "f"(m2), "f"(m3) : "memory");
}

// ---------------------------------------------------------------------------
// Kernel 4: z = relu(agg) staged fp16 hi+lo; layer-1 GEMM on tensor cores
// (2 passes: z exact to ~2^-22); layers 2+3 scalar fp32.
// sX aliases sAlo after the MMA passes to keep smem at ~50KB.
// ---------------------------------------------------------------------------
__global__ void k_final(const float* __restrict__ W1, const float* __restrict__ b1,
                        const float* __restrict__ W2, const float* __restrict__ b2,
                        const float* __restrict__ W3, const float* __restrict__ b3,
                        float* __restrict__ out, int B) {
    __shared__ __half sA[128 * 72];    // z hi [node][k]
    __shared__ __half sAlo[128 * 72];  // z lo; reused as sX [col][node] pad 136
    __shared__ __half sW1T[64 * 72];   // [n][k]
    __shared__ float sW2[64 * 16];
    __shared__ float sW3[16];
    __shared__ float sb1[64];
    __shared__ float sb2[16];
    __shared__ float sb3;

    int tid = threadIdx.x;
    int n0 = blockIdx.x * 128;

    for (int i = tid; i < 64 * 64; i += 256) {
        int k = i >> 6;
        int n = i & 63;
        sW1T[n * 72 + k] = __float2half_rn(W1[k * 64 + n]);
    }
    for (int i = tid; i < (64 * 16) / 4; i += 256)
        ((float4*)sW2)[i] = ((const float4*)W2)[i];
    if (tid < 16) { sW3[tid] = W3[tid]; sb2[tid] = b2[tid]; }
    if (tid < 64) sb1[tid] = b1[tid];
    if (tid == 0) sb3 = b3[0];

    // stage z = relu(agg) as fp16 hi + lo
    for (int i = tid; i < 128 * 16; i += 256) {
        int n = i >> 4;
        int kc = i & 15;
        int node = n0 + n;
        float4 v = make_float4(0.f, 0.f, 0.f, 0.f);
        if (node < B) {
            v = (kc < 8) ? *(const float4*)(g_agg_user + (size_t)node * D + kc * 4)
                         : *(const float4*)(g_agg_item + (size_t)node * D + (kc - 8) * 4);
        }
        v.x = fmaxf(v.x, 0.f); v.y = fmaxf(v.y, 0.f);
        v.z = fmaxf(v.z, 0.f); v.w = fmaxf(v.w, 0.f);
        uint2 ph, pl;
        split_h2(v.x, v.y, ph.x, pl.x);
        split_h2(v.z, v.w, ph.y, pl.y);
        *(uint2*)(sA + n * 72 + kc * 4) = ph;
        *(uint2*)(sAlo + n * 72 + kc * 4) = pl;
    }
    __syncthreads();

    int lane = tid & 31;
    int warp = tid >> 5;
    int g = lane >> 2;
    int tig = lane & 3;

    const unsigned* Ww = (const unsigned*)sW1T;

    float acc[8][4];
#pragma unroll
    for (int t = 0; t < 8; t++) {
        float bc0 = sb1[t * 8 + 2 * tig];
        float bc1 = sb1[t * 8 + 2 * tig + 1];
        acc[t][0] = bc0; acc[t][1] = bc1; acc[t][2] = bc0; acc[t][3] = bc1;
    }

    int r0 = warp * 16 + g;
#pragma unroll
    for (int pass = 0; pass < 2; pass++) {
        const unsigned* Aw = (const unsigned*)(pass ? sAlo : sA);
#pragma unroll
        for (int ks = 0; ks < 4; ks++) {
            unsigned a0 = Aw[r0 * 36 + ks * 8 + tig];
            unsigned a1 = Aw[(r0 + 8) * 36 + ks * 8 + tig];
            unsigned a2 = Aw[r0 * 36 + ks * 8 + tig + 4];
            unsigned a3 = Aw[(r0 + 8) * 36 + ks * 8 + tig + 4];
#pragma unroll
            for (int t = 0; t < 8; t++) {
                unsigned b0 = Ww[(t * 8 + g) * 36 + ks * 8 + tig];
                unsigned b1 = Ww[(t * 8 + g) * 36 + ks * 8 + tig + 4];
                mma_16816(acc[t], a0, a1, a2, a3, b0, b1);
            }
        }
    }
    __syncthreads();   // all warps done reading sAlo before it becomes sX

    // x1 = relu(acc) -> sX[col][node] fp16 (aliased onto sAlo)
    __half* sX = sAlo;
    int nA = warp * 16 + g;
    int nB = nA + 8;
#pragma unroll
    for (int t = 0; t < 8; t++) {
        int col = t * 8 + 2 * tig;
        sX[col * 136 + nA] = __float2half(fmaxf(acc[t][0], 0.f));
        sX[(col + 1) * 136 + nA] = __float2half(fmaxf(acc[t][1], 0.f));
        sX[col * 136 + nB] = __float2half(fmaxf(acc[t][2], 0.f));
        sX[(col + 1) * 136 + nB] = __float2half(fmaxf(acc[t][3], 0.f));
    }
    __syncthreads();

    // layers 2+3: 2 threads per node (each 8 of the 16 mid cols)
    {
        int n = tid >> 1;
        int half = tid & 1;
        int node = n0 + n;
        float a2[8];
#pragma unroll
        for (int j = 0; j < 8; j++) a2[j] = sb2[half * 8 + j];
#pragma unroll 8
        for (int k = 0; k < 64; k++) {
            float x = __half2float(sX[k * 136 + n]);
            float4 w0 = *(const float4*)(&sW2[k * 16 + half * 8]);
            float4 w1 = *(const float4*)(&sW2[k * 16 + half * 8 + 4]);
            a2[0] += x * w0.x; a2[1] += x * w0.y; a2[2] += x * w0.z; a2[3] += x * w0.w;
            a2[4] += x * w1.x; a2[5] += x * w1.y; a2[6] += x * w1.z; a2[7] += x * w1.w;
        }
        float part = 0.f;
#pragma unroll
        for (int j = 0; j < 8; j++) part += fmaxf(a2[j], 0.f) * sW3[half * 8 + j];
        part += __shfl_xor_sync(0xffffffffu, part, 1);
        if (half == 0 && node < B) out[node] = part + sb3;
    }
}

// ---------------------------------------------------------------------------
// Launch. Detect input ordering (reference-arg order vs setup_inputs order).
// ---------------------------------------------------------------------------
extern "C" void kernel_launch(void* const* d_in, const int* in_sizes, int n_in,
                              void* d_out, int out_size) {
    bool refOrder = in_sizes[2] > 1000000;

    int iMemU, iMemI, iFeat, iTui, iTiu, iWu, iWi, iWeUI, iBeUI, iWeIU, iBeIU;
    int iTw, iTb, iW1, iB1, iW2, iB2, iW3, iB3;
    int iNidU, iNidI, iSrcUI, iDstUI, iSrcIU, iDstIU, iIdxUI, iIdxIU;

    if (refOrder) {
        iMemU = 0;  iMemI = 1;  iFeat = 2;  iTui = 3;  iTiu = 4;
        iWu = 5;    iWi = 6;    iWeUI = 7;  iBeUI = 8; iWeIU = 9; iBeIU = 10;
        iTw = 11;   iTb = 12;
        iW1 = 13;   iB1 = 14;   iW2 = 15;   iB2 = 16;  iW3 = 17;  iB3 = 18;
        iNidU = 19; iNidI = 20;
        iSrcUI = 21; iDstUI = 22; iSrcIU = 23; iDstIU = 24; iIdxUI = 25; iIdxIU = 26;
    } else {
        iMemU = 0;  iMemI = 1;  iNidU = 2;  iNidI = 3;
        iSrcUI = 4; iDstUI = 5; iSrcIU = 6; iDstIU = 7; iIdxUI = 8; iIdxIU = 9;
        iTui = 10;  iTiu = 11;  iFeat = 12;
        iWu = 13;   iWi = 14;   iWeUI = 15; iBeUI = 16; iWeIU = 17; iBeIU = 18;
        iTw = 19;   iTb = 20;
        iW1 = 21;   iB1 = 22;   iW2 = 23;   iB2 = 24;   iW3 = 25;  iB3 = 26;
    }

    const float* mem_user = (const float*)d_in[iMemU];
    const float* mem_item = (const float*)d_in[iMemI];
    const float* feat     = (const float*)d_in[iFeat];
    const float* t_ui     = (const float*)d_in[iTui];
    const float* t_iu     = (const float*)d_in[iTiu];
    const float* Wu       = (const float*)d_in[iWu];
    const float* Wi       = (const float*)d_in[iWi];
    const float* WeUI     = (const float*)d_in[iWeUI];
    const float* beUI     = (const float*)d_in[iBeUI];
    const float* WeIU     = (const float*)d_in[iWeIU];
    const float* beIU     = (const float*)d_in[iBeIU];
    const float* tw       = (const float*)d_in[iTw];
    const float* tb       = (const float*)d_in[iTb];
    const float* W1       = (const float*)d_in[iW1];
    const float* b1       = (const float*)d_in[iB1];
    const float* W2       = (const float*)d_in[iW2];
    const float* b2       = (const float*)d_in[iB2];
    const float* W3       = (const float*)d_in[iW3];
    const float* b3       = (const float*)d_in[iB3];
    const int* nid_user   = (const int*)d_in[iNidU];
    const int* nid_item   = (const int*)d_in[iNidI];
    const int* src_ui     = (const int*)d_in[iSrcUI];
    const int* dst_ui     = (const int*)d_in[iDstUI];
    const int* src_iu     = (const int*)d_in[iSrcIU];
    const int* dst_iu     = (const int*)d_in[iDstIU];
    const int* idx_ui     = (const int*)d_in[iIdxUI];
    const int* idx_iu     = (const int*)d_in[iIdxIU];

    int B  = in_sizes[iNidU];
    int E  = in_sizes[iSrcUI];
    int NE = in_sizes[iFeat] / F;

    k_h<<<(B + 255) / 256, 256>>>(mem_user, mem_item, nid_user, nid_item, Wu, Wi, B);

    k_proj<<<(NE + 127) / 128, 256>>>(feat, WeUI, beUI, WeIU, beIU, NE);

    long total_edges = 2L * E;
    int nb_e = (int)((total_edges + 63) / 64);
    k_edge<<<nb_e, 256>>>(src_ui, dst_ui, idx_ui, t_ui,
                          src_iu, dst_iu, idx_iu, t_iu,
                          tw, tb, E, 0);
    k_edge<<<nb_e, 256>>>(src_ui, dst_ui, idx_ui, t_ui,
                          src_iu, dst_iu, idx_iu, t_iu,
                          tw, tb, E, 1);

    k_final<<<(B + 127) / 128, 256>>>(W1, b1, W2, b2, W3, b3,
                                      (float*)d_out, B);
}

// round 14
// speedup vs baseline: 1.4317x; 1.0588x over previous
#include <cuda_runtime.h>
#include <cuda_fp16.h>
#include <math.h>

#define D 32
#define HP 16            // half-plane width (dims per edge pass)
#define F 64
#define MAXB 262144
#define MAXNE 500000

// Scratch (device globals — no allocation allowed)
// h and proj stored PLANE-MAJOR: [plane][row][16] so each edge pass gathers
// a 32B-aligned half-row and the per-pass working set fits in L2.
__device__ float g_agg_user[MAXB * D];        // seeded with h_user, edges add in
__device__ float g_agg_item[MAXB * D];        // seeded with h_item
__device__ __half g_hh_user[2 * MAXB * HP];   // fp16 h planes for edge gather
__device__ __half g_hh_item[2 * MAXB * HP];
__device__ __half g_proj_ui[2 * MAXNE * HP];  // fp16 proj planes
__device__ __half g_proj_iu[2 * MAXNE * HP];

// ---------------------------------------------------------------------------
// mma.m16n8k16 fp16 -> fp32 helper
// ---------------------------------------------------------------------------
__device__ __forceinline__ void mma_16816(float* c, unsigned a0, unsigned a1,
                                          unsigned a2, unsigned a3,
                                          unsigned b0, unsigned b1) {
    asm volatile(
        "mma.sync.aligned.m16n8k16.row.col.f32.f16.f16.f32 "
        "{%0,%1,%2,%3}, {%4,%5,%6,%7}, {%8,%9}, {%0,%1,%2,%3};"
        : "+f"(c[0]), "+f"(c[1]), "+f"(c[2]), "+f"(c[3])
        : "r"(a0), "r"(a1), "r"(a2), "r"(a3), "r"(b0), "r"(b1));
}

// split float into fp16 hi + fp16 lo residual
__device__ __forceinline__ void split_h2(float x, float y,
                                         unsigned& hi, unsigned& lo) {
    __half hx = __float2half_rn(x);
    __half hy = __float2half_rn(y);
    __half lx = __float2half_rn(x - __half2float(hx));
    __half ly = __float2half_rn(y - __half2float(hy));
    __half2 h = __halves2half2(hx, hy);
    __half2 l = __halves2half2(lx, ly);
    hi = *(unsigned*)&h;
    lo = *(unsigned*)&l;
}

__device__ __forceinline__ unsigned pack_relu_h2(float x, float y) {
    __half2 h = __floats2half2_rn(fmaxf(x, 0.f), fmaxf(y, 0.f));
    return *(unsigned*)&h;
}

// ---------------------------------------------------------------------------
// Kernel 1: h = mem[ids] @ W on TENSOR CORES (3-pass hi/lo: exact to ~2^-21).
// Block = 256 threads handles 256 nodes; user then item phase (smem reused).
// Writes fp32 agg seed + fp16 plane-major h tables. No shfl anywhere.
// ---------------------------------------------------------------------------
__global__ void k_h(const float* __restrict__ mem_user,
                    const float* __restrict__ mem_item,
                    const int* __restrict__ nid_user,
                    const int* __restrict__ nid_item,
                    const float* __restrict__ Wu,
                    const float* __restrict__ Wi,
                    int B) {
    __shared__ __half sM[256 * 40];     // gathered mem rows, fp16 hi
    __shared__ __half sMlo[256 * 40];   // fp16 lo residual
    __shared__ __half sWT[32 * 40];     // W^T [n][k] hi (one type at a time)
    __shared__ __half sWTlo[32 * 40];   // W^T lo
    __shared__ int sIds[512];           // user ids [0..255], item ids [256..511]

    int tid = threadIdx.x;
    int n0 = blockIdx.x * 256;
    int lane = tid & 31;
    int warp = tid >> 5;
    int g = lane >> 2;
    int tig = lane & 3;

    // stage both id arrays
    {
        int node = n0 + tid;
        sIds[tid] = (node < B) ? nid_user[node] : 0;
        sIds[256 + tid] = (node < B) ? nid_item[node] : 0;
    }

    for (int type = 0; type < 2; type++) {
        const float* mem = type ? mem_item : mem_user;
        const float* W = type ? Wi : Wu;
        float* agg = type ? g_agg_item : g_agg_user;
        __half* hh = type ? g_hh_item : g_hh_user;

        __syncthreads();   // ids ready (iter0) / prev mma done reading smem

        // stage W^T hi/lo: sWT[n*40+k] = W[k*32+n]
        for (int i = tid; i < 32 * 32; i += 256) {
            int k = i >> 5;
            int n = i & 31;
            float v = W[k * 32 + n];
            __half hi = __float2half_rn(v);
            sWT[n * 40 + k] = hi;
            sWTlo[n * 40 + k] = __float2half_rn(v - __half2float(hi));
        }

        // gather 256 mem rows (8 float4-chunks each) as fp16 hi/lo
        for (int it = 0; it < 8; it++) {
            int idx = tid + it * 256;
            int row = idx >> 3;
            int c = idx & 7;
            int nid = sIds[type * 256 + row];
            float4 v = *(const float4*)(mem + (size_t)nid * D + c * 4);
            uint2 ph, pl;
            split_h2(v.x, v.y, ph.x, pl.x);
            split_h2(v.z, v.w, ph.y, pl.y);
            *(uint2*)(sM + row * 40 + c * 4) = ph;
            *(uint2*)(sMlo + row * 40 + c * 4) = pl;
        }
        __syncthreads();

        // mma: warp covers rows [warp*32, warp*32+32); 2 mtiles x 4 ntiles
        float acc[2][4][4];
#pragma unroll
        for (int m = 0; m < 2; m++)
#pragma unroll
            for (int nt = 0; nt < 4; nt++)
#pragma unroll
                for (int j = 0; j < 4; j++) acc[m][nt][j] = 0.f;

#pragma unroll
        for (int pass = 0; pass < 3; pass++) {
            const unsigned* Aw = (const unsigned*)(pass == 1 ? sMlo : sM);
            const unsigned* Ww = (const unsigned*)(pass == 2 ? sWTlo : sWT);
#pragma unroll
            for (int m = 0; m < 2; m++) {
                int rb = warp * 32 + m * 16 + g;
#pragma unroll
                for (int ks = 0; ks < 2; ks++) {
                    unsigned a0 = Aw[rb * 20 + ks * 8 + tig];
                    unsigned a1 = Aw[(rb + 8) * 20 + ks * 8 + tig];
                    unsigned a2 = Aw[rb * 20 + ks * 8 + tig + 4];
                    unsigned a3 = Aw[(rb + 8) * 20 + ks * 8 + tig + 4];
#pragma unroll
                    for (int nt = 0; nt < 4; nt++) {
                        unsigned b0 = Ww[(nt * 8 + g) * 20 + ks * 8 + tig];
                        unsigned b1 = Ww[(nt * 8 + g) * 20 + ks * 8 + tig + 4];
                        mma_16816(acc[m][nt], a0, a1, a2, a3, b0, b1);
                    }
                }
            }
        }

        // epilogue: agg (fp32) + hh (fp16 plane-major)
#pragma unroll
        for (int m = 0; m < 2; m++) {
            int rA = warp * 32 + m * 16 + g;
            int rB = rA + 8;
            int nodeA = n0 + rA;
            int nodeB = n0 + rB;
#pragma unroll
            for (int nt = 0; nt < 4; nt++) {
                int col = nt * 8 + 2 * tig;      // even
                int plane = col >> 4;
                int off = col & 15;
                float c0 = acc[m][nt][0], c1 = acc[m][nt][1];
                float c2 = acc[m][nt][2], c3 = acc[m][nt][3];
                if (nodeA < B) {
                    *(float2*)(agg + (size_t)nodeA * D + col) = make_float2(c0, c1);
                    *(__half2*)(hh + ((size_t)plane * MAXB + nodeA) * HP + off) =
                        __floats2half2_rn(c0, c1);
                }
                if (nodeB < B) {
                    *(float2*)(agg + (size_t)nodeB * D + col) = make_float2(c2, c3);
                    *(__half2*)(hh + ((size_t)plane * MAXB + nodeB) * HP + off) =
                        __floats2half2_rn(c2, c3);
                }
            }
        }
    }
}

// ---------------------------------------------------------------------------
// Kernel 2: proj = feat @ We + be for BOTH edge types, tensor cores.
// Tile: 128 rows x 64 cols (cols 0..31 -> ui, 32..63 -> iu), K=64.
// Epilogue: stage fp16 tile in smem, coalesced 16B plane-major writeout.
// ---------------------------------------------------------------------------
__global__ void k_proj(const float* __restrict__ feat,
                       const float* __restrict__ We0, const float* __restrict__ be0,
                       const float* __restrict__ We1, const float* __restrict__ be1,
                       int NE) {
    __shared__ __half sA[128 * 72];      // feat fp16 [row][k]; reused as out tile
    __shared__ __half sWT[64 * 72];      // [n][k]
    __shared__ float sb[64];

    int tid = threadIdx.x;
    int row0 = blockIdx.x * 128;

    for (int i = tid; i < 64 * 64; i += 256) {
        int k = i >> 6;
        int n = i & 63;
        float v = (n < 32) ? We0[k * 32 + n] : We1[k * 32 + (n - 32)];
        sWT[n * 72 + k] = __float2half_rn(v);
    }
    if (tid < 32) { sb[tid] = be0[tid]; sb[32 + tid] = be1[tid]; }

    for (int i = tid; i < 128 * 16; i += 256) {
        int r = i >> 4;
        int k0 = (i & 15) * 4;
        int gr = row0 + r;
        float4 v = make_float4(0.f, 0.f, 0.f, 0.f);
        if (gr < NE) v = *(const float4*)(feat + (size_t)gr * F + k0);
        __half2 h01 = __floats2half2_rn(v.x, v.y);
        __half2 h23 = __floats2half2_rn(v.z, v.w);
        uint2 pk;
        pk.x = *(unsigned*)&h01;
        pk.y = *(unsigned*)&h23;
        *(uint2*)(sA + r * 72 + k0) = pk;
    }
    __syncthreads();

    int lane = tid & 31;
    int warp = tid >> 5;
    int g = lane >> 2;       // 0..7
    int tig = lane & 3;      // 0..3

    const unsigned* Aw = (const unsigned*)sA;    // 36 words per row
    const unsigned* Ww = (const unsigned*)sWT;   // 36 words per n

    float acc[8][4];
#pragma unroll
    for (int t = 0; t < 8; t++) {
        float bc0 = sb[t * 8 + 2 * tig];
        float bc1 = sb[t * 8 + 2 * tig + 1];
        acc[t][0] = bc0; acc[t][1] = bc1; acc[t][2] = bc0; acc[t][3] = bc1;
    }

    int r0 = warp * 16 + g;
#pragma unroll
    for (int ks = 0; ks < 4; ks++) {
        unsigned a0 = Aw[r0 * 36 + ks * 8 + tig];
        unsigned a1 = Aw[(r0 + 8) * 36 + ks * 8 + tig];
        unsigned a2 = Aw[r0 * 36 + ks * 8 + tig + 4];
        unsigned a3 = Aw[(r0 + 8) * 36 + ks * 8 + tig + 4];
#pragma unroll
        for (int t = 0; t < 8; t++) {
            unsigned b0 = Ww[(t * 8 + g) * 36 + ks * 8 + tig];
            unsigned b1 = Ww[(t * 8 + g) * 36 + ks * 8 + tig + 4];
            mma_16816(acc[t], a0, a1, a2, a3, b0, b1);
        }
    }
    __syncthreads();   // everyone done reading sA before it becomes the out tile

    // stage result tile in smem: sA[row][col] fp16, stride 72
    int rA = warp * 16 + g;
    int rB = rA + 8;
#pragma unroll
    for (int t = 0; t < 8; t++) {
        int col = t * 8 + 2 * tig;   // even -> 4B aligned
        *(__half2*)(sA + rA * 72 + col) = __floats2half2_rn(acc[t][0], acc[t][1]);
        *(__half2*)(sA + rB * 72 + col) = __floats2half2_rn(acc[t][2], acc[t][3]);
    }
    __syncthreads();

    // coalesced writeout: 1024 16B-chunks (128 rows x 2 types x 2 planes x 2)
    for (int i = tid; i < 1024; i += 256) {
        int r = i & 127;             // row within tile
        int c8 = i >> 7;             // 0..7 : which 8-half chunk
        int col = c8 * 8;            // source col in tile (0..56)
        int gr = row0 + r;
        if (gr >= NE) continue;
        uint4 v = *(const uint4*)(sA + r * 72 + col);   // 16B-aligned (144*r+2*col)
        __half* base = (col < 32) ? g_proj_ui : g_proj_iu;
        int c = col & 31;            // col within type
        int plane = c >> 4;          // 0 or 1
        int off = c & 15;            // 0 or 8
        *(uint4*)(base + ((size_t)plane * MAXNE + gr) * HP + off) = v;
    }
}

// ---------------------------------------------------------------------------
// Kernel 3: per-edge message + scatter for ONE dim-plane (16 dims).
// 4 lanes per edge, lane handles 4 dims -> one red.global.add.v4.f32.
// Launched twice (plane 0, plane 1) SEQUENTIALLY so the per-pass working
// set (h half + proj half + agg half ~= 80MB) fits in L2.
// ---------------------------------------------------------------------------
__global__ void k_edge(const int* __restrict__ src_ui, const int* __restrict__ dst_ui,
                       const int* __restrict__ idx_ui, const float* __restrict__ t_ui,
                       const int* __restrict__ src_iu, const int* __restrict__ dst_iu,
                       const int* __restrict__ idx_iu, const float* __restrict__ t_iu,
                       const float* __restrict__ time_w, const float* __restrict__ time_b,
                       int E, int plane) {
    int tid = threadIdx.x;
    int lane = tid & 31;
    int warp = tid >> 5;
    int q = lane & 3;        // dim quad within the 16-dim plane
    int s = lane >> 2;       // edge slot within warp (0..7)
    long e = (long)blockIdx.x * 64 + warp * 8 + s;
    if (e >= 2L * E) return;

    const int *srcA, *dstA, *idxA;
    const float* tA;
    const __half* hh;
    const __half* proj;
    float* agg;
    int ei;
    if (e < E) {
        ei = (int)e;
        srcA = src_ui; dstA = dst_ui; idxA = idx_ui; tA = t_ui;
        hh = g_hh_user; proj = g_proj_ui; agg = g_agg_item;
    } else {
        ei = (int)(e - E);
        srcA = src_iu; dstA = dst_iu; idxA = idx_iu; tA = t_iu;
        hh = g_hh_item; proj = g_proj_iu; agg = g_agg_user;
    }
    int srch = srcA[ei];
    int dst = dstA[ei];
    int fid = idxA[ei];
    float t = tA[ei];

    const __half2* hp = (const __half2*)(hh + ((size_t)plane * MAXB + srch) * HP + q * 4);
    float2 h01 = __half22float2(hp[0]);
    float2 h23 = __half22float2(hp[1]);
    const __half2* pp = (const __half2*)(proj + ((size_t)plane * MAXNE + fid) * HP + q * 4);
    float2 p01 = __half22float2(pp[0]);
    float2 p23 = __half22float2(pp[1]);
    int dq = plane * HP + q * 4;
    float4 tw = *(const float4*)(time_w + dq);
    float4 tb = *(const float4*)(time_b + dq);

    float m0 = h01.x + p01.x + __cosf(fmaf(t, tw.x, tb.x));
    float m1 = h01.y + p01.y + __cosf(fmaf(t, tw.y, tb.y));
    float m2 = h23.x + p23.x + __cosf(fmaf(t, tw.z, tb.z));
    float m3 = h23.y + p23.y + __cosf(fmaf(t, tw.w, tb.w));

    float* p = agg + (size_t)dst * D + dq;
    asm volatile("red.global.add.v4.f32 [%0], {%1, %2, %3, %4};"
                 :: "l"(p), "f"(m0), "f"(m1), "f"(m2), "f"(m3) : "memory");
}

// ---------------------------------------------------------------------------
// Kernel 4: z = relu(agg) staged fp16 hi+lo; layer-1 GEMM on tensor cores
// (2 passes); layer-2 ALSO on tensor cores, x1 stays in registers (C-frag of
// layer-1 == A-frag of layer-2); layer-3 = dot + 2 shfl. No x1 smem trip.
// ---------------------------------------------------------------------------
__global__ void k_final(const float* __restrict__ W1, const float* __restrict__ b1,
                        const float* __restrict__ W2, const float* __restrict__ b2,
                        const float* __restrict__ W3, const float* __restrict__ b3,
                        float* __restrict__ out, int B) {
    __shared__ __half sA[128 * 72];    // z hi [node][k]
    __shared__ __half sAlo[128 * 72];  // z lo
    __shared__ __half sW1T[64 * 72];   // [n][k]
    __shared__ __half sW2T[16 * 72];   // [n][k]
    __shared__ float sW3[16];
    __shared__ float sb1[64];
    __shared__ float sb2[16];
    __shared__ float sb3;

    int tid = threadIdx.x;
    int n0 = blockIdx.x * 128;

    for (int i = tid; i < 64 * 64; i += 256) {
        int k = i >> 6;
        int n = i & 63;
        sW1T[n * 72 + k] = __float2half_rn(W1[k * 64 + n]);
    }
    for (int i = tid; i < 16 * 64; i += 256) {
        int n = i >> 6;
        int k = i & 63;
        sW2T[n * 72 + k] = __float2half_rn(W2[k * 16 + n]);
    }
    if (tid < 16) { sW3[tid] = W3[tid]; sb2[tid] = b2[tid]; }
    if (tid < 64) sb1[tid] = b1[tid];
    if (tid == 0) sb3 = b3[0];

    // stage z = relu(agg) as fp16 hi + lo
    for (int i = tid; i < 128 * 16; i += 256) {
        int n = i >> 4;
        int kc = i & 15;
        int node = n0 + n;
        float4 v = make_float4(0.f, 0.f, 0.f, 0.f);
        if (node < B) {
            v = (kc < 8) ? *(const float4*)(g_agg_user + (size_t)node * D + kc * 4)
                         : *(const float4*)(g_agg_item + (size_t)node * D + (kc - 8) * 4);
        }
        v.x = fmaxf(v.x, 0.f); v.y = fmaxf(v.y, 0.f);
        v.z = fmaxf(v.z, 0.f); v.w = fmaxf(v.w, 0.f);
        uint2 ph, pl;
        split_h2(v.x, v.y, ph.x, pl.x);
        split_h2(v.z, v.w, ph.y, pl.y);
        *(uint2*)(sA + n * 72 + kc * 4) = ph;
        *(uint2*)(sAlo + n * 72 + kc * 4) = pl;
    }
    __syncthreads();

    int lane = tid & 31;
    int warp = tid >> 5;
    int g = lane >> 2;
    int tig = lane & 3;

    const unsigned* Ww = (const unsigned*)sW1T;

    // layer 1: acc[t] covers (rows warp*16+g, +8) x (cols t*8+2tig, +1)
    float acc[8][4];
#pragma unroll
    for (int t = 0; t < 8; t++) {
        float bc0 = sb1[t * 8 + 2 * tig];
        float bc1 = sb1[t * 8 + 2 * tig + 1];
        acc[t][0] = bc0; acc[t][1] = bc1; acc[t][2] = bc0; acc[t][3] = bc1;
    }

    int r0 = warp * 16 + g;
#pragma unroll
    for (int pass = 0; pass < 2; pass++) {
        const unsigned* Aw = (const unsigned*)(pass ? sAlo : sA);
#pragma unroll
        for (int ks = 0; ks < 4; ks++) {
            unsigned a0 = Aw[r0 * 36 + ks * 8 + tig];
            unsigned a1 = Aw[(r0 + 8) * 36 + ks * 8 + tig];
            unsigned a2 = Aw[r0 * 36 + ks * 8 + tig + 4];
            unsigned a3 = Aw[(r0 + 8) * 36 + ks * 8 + tig + 4];
#pragma unroll
            for (int t = 0; t < 8; t++) {
                unsigned b0 = Ww[(t * 8 + g) * 36 + ks * 8 + tig];
                unsigned b1 = Ww[(t * 8 + g) * 36 + ks * 8 + tig + 4];
                mma_16816(acc[t], a0, a1, a2, a3, b0, b1);
            }
        }
    }

    // layer 2 on tensor cores: relu(acc) repacked directly as A-frags.
    // k-step j (k=16j..16j+15): a0 = tile 2j rows g, a1 = tile 2j rows g+8,
    // a2 = tile 2j+1 rows g, a3 = tile 2j+1 rows g+8.
    float acc2[2][4];
#pragma unroll
    for (int nt = 0; nt < 2; nt++) {
        float bc0 = sb2[nt * 8 + 2 * tig];
        float bc1 = sb2[nt * 8 + 2 * tig + 1];
        acc2[nt][0] = bc0; acc2[nt][1] = bc1; acc2[nt][2] = bc0; acc2[nt][3] = bc1;
    }
    const unsigned* W2w = (const unsigned*)sW2T;
#pragma unroll
    for (int j = 0; j < 4; j++) {
        unsigned a0 = pack_relu_h2(acc[2 * j][0], acc[2 * j][1]);
        unsigned a1 = pack_relu_h2(acc[2 * j][2], acc[2 * j][3]);
        unsigned a2 = pack_relu_h2(acc[2 * j + 1][0], acc[2 * j + 1][1]);
        unsigned a3 = pack_relu_h2(acc[2 * j + 1][2], acc[2 * j + 1][3]);
#pragma unroll
        for (int nt = 0; nt < 2; nt++) {
            unsigned b0 = W2w[(nt * 8 + g) * 36 + j * 8 + tig];
            unsigned b1 = W2w[(nt * 8 + g) * 36 + j * 8 + tig + 4];
            mma_16816(acc2[nt], a0, a1, a2, a3, b0, b1);
        }
    }

    // layer 3: per-lane partial dot over cols (nt*8+2tig, +1), reduce over tig
    float pA = 0.f, pB = 0.f;
#pragma unroll
    for (int nt = 0; nt < 2; nt++) {
        int c = nt * 8 + 2 * tig;
        pA += fmaxf(acc2[nt][0], 0.f) * sW3[c] + fmaxf(acc2[nt][1], 0.f) * sW3[c + 1];
        pB += fmaxf(acc2[nt][2], 0.f) * sW3[c] + fmaxf(acc2[nt][3], 0.f) * sW3[c + 1];
    }
    pA += __shfl_xor_sync(0xffffffffu, pA, 1);
    pA += __shfl_xor_sync(0xffffffffu, pA, 2);
    pB += __shfl_xor_sync(0xffffffffu, pB, 1);
    pB += __shfl_xor_sync(0xffffffffu, pB, 2);
    if (tig == 0) {
        int nodeA = n0 + warp * 16 + g;
        int nodeB = nodeA + 8;
        if (nodeA < B) out[nodeA] = pA + sb3;
        if (nodeB < B) out[nodeB] = pB + sb3;
    }
}

// ---------------------------------------------------------------------------
// Launch. Detect input ordering (reference-arg order vs setup_inputs order).
// ---------------------------------------------------------------------------
extern "C" void kernel_launch(void* const* d_in, const int* in_sizes, int n_in,
                              void* d_out, int out_size) {
    bool refOrder = in_sizes[2] > 1000000;

    int iMemU, iMemI, iFeat, iTui, iTiu, iWu, iWi, iWeUI, iBeUI, iWeIU, iBeIU;
    int iTw, iTb, iW1, iB1, iW2, iB2, iW3, iB3;
    int iNidU, iNidI, iSrcUI, iDstUI, iSrcIU, iDstIU, iIdxUI, iIdxIU;

    if (refOrder) {
        iMemU = 0;  iMemI = 1;  iFeat = 2;  iTui = 3;  iTiu = 4;
        iWu = 5;    iWi = 6;    iWeUI = 7;  iBeUI = 8; iWeIU = 9; iBeIU = 10;
        iTw = 11;   iTb = 12;
        iW1 = 13;   iB1 = 14;   iW2 = 15;   iB2 = 16;  iW3 = 17;  iB3 = 18;
        iNidU = 19; iNidI = 20;
        iSrcUI = 21; iDstUI = 22; iSrcIU = 23; iDstIU = 24; iIdxUI = 25; iIdxIU = 26;
    } else {
        iMemU = 0;  iMemI = 1;  iNidU = 2;  iNidI = 3;
        iSrcUI = 4; iDstUI = 5; iSrcIU = 6; iDstIU = 7; iIdxUI = 8; iIdxIU = 9;
        iTui = 10;  iTiu = 11;  iFeat = 12;
        iWu = 13;   iWi = 14;   iWeUI = 15; iBeUI = 16; iWeIU = 17; iBeIU = 18;
        iTw = 19;   iTb = 20;
        iW1 = 21;   iB1 = 22;   iW2 = 23;   iB2 = 24;   iW3 = 25;  iB3 = 26;
    }

    const float* mem_user = (const float*)d_in[iMemU];
    const float* mem_item = (const float*)d_in[iMemI];
    const float* feat     = (const float*)d_in[iFeat];
    const float* t_ui     = (const float*)d_in[iTui];
    const float* t_iu     = (const float*)d_in[iTiu];
    const float* Wu       = (const float*)d_in[iWu];
    const float* Wi       = (const float*)d_in[iWi];
    const float* WeUI     = (const float*)d_in[iWeUI];
    const float* beUI     = (const float*)d_in[iBeUI];
    const float* WeIU     = (const float*)d_in[iWeIU];
    const float* beIU     = (const float*)d_in[iBeIU];
    const float* tw       = (const float*)d_in[iTw];
    const float* tb       = (const float*)d_in[iTb];
    const float* W1       = (const float*)d_in[iW1];
    const float* b1       = (const float*)d_in[iB1];
    const float* W2       = (const float*)d_in[iW2];
    const float* b2       = (const float*)d_in[iB2];
    const float* W3       = (const float*)d_in[iW3];
    const float* b3       = (const float*)d_in[iB3];
    const int* nid_user   = (const int*)d_in[iNidU];
    const int* nid_item   = (const int*)d_in[iNidI];
    const int* src_ui     = (const int*)d_in[iSrcUI];
    const int* dst_ui     = (const int*)d_in[iDstUI];
    const int* src_iu     = (const int*)d_in[iSrcIU];
    const int* dst_iu     = (const int*)d_in[iDstIU];
    const int* idx_ui     = (const int*)d_in[iIdxUI];
    const int* idx_iu     = (const int*)d_in[iIdxIU];

    int B  = in_sizes[iNidU];
    int E  = in_sizes[iSrcUI];
    int NE = in_sizes[iFeat] / F;

    k_h<<<(B + 255) / 256, 256>>>(mem_user, mem_item, nid_user, nid_item, Wu, Wi, B);

    k_proj<<<(NE + 127) / 128, 256>>>(feat, WeUI, beUI, WeIU, beIU, NE);

    long total_edges = 2L * E;
    int nb_e = (int)((total_edges + 63) / 64);
    k_edge<<<nb_e, 256>>>(src_ui, dst_ui, idx_ui, t_ui,
                          src_iu, dst_iu, idx_iu, t_iu,
                          tw, tb, E, 0);
    k_edge<<<nb_e, 256>>>(src_ui, dst_ui, idx_ui, t_ui,
                          src_iu, dst_iu, idx_iu, t_iu,
                          tw, tb, E, 1);

    k_final<<<(B + 127) / 128, 256>>>(W1, b1, W2, b2, W3, b3,
                                      (float*)d_out, B);
}